// round 14
// baseline (speedup 1.0000x reference)
#include <cuda_runtime.h>
#include <cuda_bf16.h>
#include <math.h>

#define TQ 128
#define TK 256
#define BB 8
#define HD 512

#define XROWS (TK*BB + TQ*BB)

__device__ float g_kp[TK*BB*HD];
__device__ float g_qp[TQ*BB*HD];
__device__ int   g_klist[BB*TK];
__device__ int   g_kcnt[BB];
__device__ unsigned char g_maskdec[BB*TK];
__device__ __align__(16) __nv_bfloat16 g_xh[XROWS*HD];
__device__ __align__(16) __nv_bfloat16 g_xl[XROWS*HD];
__device__ __align__(16) __nv_bfloat16 g_wh[2*HD*HD];
__device__ __align__(16) __nv_bfloat16 g_wl[2*HD*HD];

__device__ __forceinline__ unsigned pack_bf2(__nv_bfloat16 a, __nv_bfloat16 b) {
    __nv_bfloat162 t(a, b);
    return *(unsigned*)&t;
}

// ---------------------------------------------------------------------------
// mask_prep: parallel mask-dtype detect + per-b order-preserving compaction.
// ---------------------------------------------------------------------------
__global__ void __launch_bounds__(256) mask_prep(const void* __restrict__ mask) {
    __shared__ int s_isfloat, s_isbig;
    const int tid = threadIdx.x;
    if (tid == 0) { s_isfloat = 0; s_isbig = 0; }
    __syncthreads();
    for (int i = tid; i < 512; i += 256) {
        unsigned v = ((const unsigned*)mask)[i];
        if (v == 0x3f800000u) s_isfloat = 1;
        else if (v > 1u)      s_isbig = 1;
    }
    __syncthreads();
    const int mode = s_isfloat ? 2 : (s_isbig ? 1 : 0);
    const int w = tid >> 5, lane = tid & 31;
    if (w < BB) {
        const int b = w;
        int base = 0;
        #pragma unroll
        for (int c = 0; c < 8; c++) {
            const int k = c * 32 + lane;
            int mk;
            if (mode == 2)      mk = ((const float*)mask)[k*BB + b] != 0.0f;
            else if (mode == 1) mk = ((const unsigned char*)mask)[k*BB + b] != 0;
            else                mk = ((const int*)mask)[k*BB + b] != 0;
            g_maskdec[b*TK + k] = (unsigned char)mk;
            unsigned bal = __ballot_sync(0xffffffffu, !mk);
            if (!mk) {
                int pos = base + __popc(bal & ((1u << lane) - 1u));
                g_klist[b*TK + pos] = k;
            }
            base += __popc(bal);
        }
        if (lane == 0) g_kcnt[b] = base;
    }
}

// ---------------------------------------------------------------------------
// convert: pure streaming fp32 -> bf16 hi/lo split for c_key, query, W1.
// ---------------------------------------------------------------------------
__global__ void __launch_bounds__(256) convert_kernel(
        const float* __restrict__ query,
        const float* __restrict__ c_key,
        const float* __restrict__ W1) {
    const int NCK = (TK*BB*HD)/4;
    const int NQ  = (TQ*BB*HD)/4;
    const int NW  = (2*HD*HD)/4;
    const int total = NCK + NQ + NW;
    const int stride = gridDim.x * blockDim.x;
    for (int i = blockIdx.x*blockDim.x + threadIdx.x; i < total; i += stride) {
        const float4* src; __nv_bfloat16 *H, *L; int e;
        if (i < NCK)          { src = (const float4*)c_key + i;       e = i*4;                  H = g_xh; L = g_xl; }
        else if (i < NCK+NQ)  { src = (const float4*)query + (i-NCK); e = (i-NCK)*4 + TK*BB*HD; H = g_xh; L = g_xl; }
        else                  { src = (const float4*)W1 + (i-NCK-NQ); e = (i-NCK-NQ)*4;         H = g_wh; L = g_wl; }
        float4 v = *src;
        __nv_bfloat16 hx = __float2bfloat16(v.x), hy = __float2bfloat16(v.y);
        __nv_bfloat16 hz = __float2bfloat16(v.z), hw = __float2bfloat16(v.w);
        __nv_bfloat16 lx = __float2bfloat16(v.x - __bfloat162float(hx));
        __nv_bfloat16 ly = __float2bfloat16(v.y - __bfloat162float(hy));
        __nv_bfloat16 lz = __float2bfloat16(v.z - __bfloat162float(hz));
        __nv_bfloat16 lw = __float2bfloat16(v.w - __bfloat162float(hw));
        uint2 hp = make_uint2(pack_bf2(hx,hy), pack_bf2(hz,hw));
        uint2 lp = make_uint2(pack_bf2(lx,ly), pack_bf2(lz,lw));
        *(uint2*)&H[e] = hp;
        *(uint2*)&L[e] = lp;
    }
}

// ---------------------------------------------------------------------------
// Projection GEMM (bf16 hi/lo split, 3 MMA products).  128x64 tile, 256 thr.
// ---------------------------------------------------------------------------
#define LDSM4(R, addr) \
    asm volatile("ldmatrix.sync.aligned.m8n8.x4.shared.b16 {%0,%1,%2,%3}, [%4];" \
        : "=r"(R[0]),"=r"(R[1]),"=r"(R[2]),"=r"(R[3]) : "r"(addr))
#define LDSM4T(R, addr) \
    asm volatile("ldmatrix.sync.aligned.m8n8.x4.trans.shared.b16 {%0,%1,%2,%3}, [%4];" \
        : "=r"(R[0]),"=r"(R[1]),"=r"(R[2]),"=r"(R[3]) : "r"(addr))
#define MMA_BF16(C, A, B0, B1) \
    asm volatile("mma.sync.aligned.m16n8k16.row.col.f32.bf16.bf16.f32 " \
        "{%0,%1,%2,%3},{%4,%5,%6,%7},{%8,%9},{%0,%1,%2,%3};" \
        : "+f"(C[0]),"+f"(C[1]),"+f"(C[2]),"+f"(C[3]) \
        : "r"(A[0]),"r"(A[1]),"r"(A[2]),"r"(A[3]), "r"(B0),"r"(B1))

__global__ void __launch_bounds__(256) proj_mma(const float* __restrict__ b1) {
    __shared__ __align__(16) __nv_bfloat16 Ah[128*64], Al[128*64];
    __shared__ __align__(16) __nv_bfloat16 Bh[64*64],  Bl[64*64];
    const int tid = threadIdx.x, w = tid >> 5, l = tid & 31;
    const int by = blockIdx.y, bn = blockIdx.x * 64;
    const int isQ = (by >= 16);
    const int xrow0 = isQ ? (TK*BB + (by-16)*128) : by*128;
    const int wrow0 = isQ ? HD : 0;
    float* C = isQ ? g_qp : g_kp;
    const int crow0 = isQ ? (by-16)*128 : by*128;
    float acc[8][4] = {};

    for (int kc = 0; kc < HD; kc += 64) {
        #pragma unroll
        for (int t = 0; t < 4; t++) {
            int idx = tid + t*256;
            int r = idx >> 3, c = idx & 7;
            int so = r*64 + ((c ^ (r & 7)) << 3);
            size_t ge = (size_t)(xrow0 + r)*HD + kc + c*8;
            *(uint4*)&Ah[so] = *(const uint4*)&g_xh[ge];
            *(uint4*)&Al[so] = *(const uint4*)&g_xl[ge];
        }
        #pragma unroll
        for (int t = 0; t < 2; t++) {
            int idx = tid + t*256;
            int r = idx >> 3, c = idx & 7;
            int so = r*64 + ((c ^ (r & 7)) << 3);
            size_t ge = (size_t)(wrow0 + kc + r)*HD + bn + c*8;
            *(uint4*)&Bh[so] = *(const uint4*)&g_wh[ge];
            *(uint4*)&Bl[so] = *(const uint4*)&g_wl[ge];
        }
        __syncthreads();
        #pragma unroll
        for (int ks = 0; ks < 4; ks++) {
            int arow = 16*w + (l & 15);
            int ac = ks*2 + (l >> 4);
            unsigned aoff = (unsigned)((arow*64 + ((ac ^ (arow & 7)) << 3)) * 2);
            unsigned ah_a = (unsigned)__cvta_generic_to_shared(Ah) + aoff;
            unsigned al_a = (unsigned)__cvta_generic_to_shared(Al) + aoff;
            unsigned ah[4], al[4];
            LDSM4(ah, ah_a); LDSM4(al, al_a);
            #pragma unroll
            for (int nt = 0; nt < 4; nt++) {
                int brow = ks*16 + (l & 15);
                int bc = nt*2 + (l >> 4);
                unsigned boff = (unsigned)((brow*64 + ((bc ^ (brow & 7)) << 3)) * 2);
                unsigned bh_a = (unsigned)__cvta_generic_to_shared(Bh) + boff;
                unsigned bl_a = (unsigned)__cvta_generic_to_shared(Bl) + boff;
                unsigned bh[4], bl[4];
                LDSM4T(bh, bh_a); LDSM4T(bl, bl_a);
                MMA_BF16(acc[2*nt],   ah, bh[0], bh[1]);
                MMA_BF16(acc[2*nt],   ah, bl[0], bl[1]);
                MMA_BF16(acc[2*nt],   al, bh[0], bh[1]);
                MMA_BF16(acc[2*nt+1], ah, bh[2], bh[3]);
                MMA_BF16(acc[2*nt+1], ah, bl[2], bl[3]);
                MMA_BF16(acc[2*nt+1], al, bh[2], bh[3]);
            }
        }
        __syncthreads();
    }
    const int g = l >> 2, tig = l & 3;
    const int row = crow0 + 16*w + g;
    #pragma unroll
    for (int t = 0; t < 8; t++) {
        const int col = bn + t*8 + tig*2;
        float v0 = 0.f, v1 = 0.f;
        if (isQ) { v0 = b1[col]; v1 = b1[col+1]; }
        C[(size_t)row*HD + col]       = acc[t][0] + v0;
        C[(size_t)row*HD + col+1]     = acc[t][1] + v1;
        C[(size_t)(row+8)*HD + col]   = acc[t][2] + v0;
        C[(size_t)(row+8)*HD + col+1] = acc[t][3] + v1;
    }
}

// ---------------------------------------------------------------------------
__device__ __forceinline__ float tanha(float x) {
    float y;
    asm("tanh.approx.f32 %0, %1;" : "=f"(y) : "f"(x));
    return y;
}

// ---------------------------------------------------------------------------
// Fused score + masked softmax + ant_vec.  32 warps, h-split.
// warp w: q = w&7, hsub = w>>3 (16-h slice of each staged 64-h chunk).
// Lane = key; acc[8] covers ALL key-chunks (qv/wv amortized 8x, no shuffles).
// Partial scores over 4 hsubs reduced via sc_p.  Grid (16,8) = 128 blocks.
// ---------------------------------------------------------------------------
#define KPS 65       // kp_s row stride (floats), odd => conflict-free
__global__ void __launch_bounds__(1024, 1) score_kernel(
        const float* __restrict__ c_key,
        const float* __restrict__ W2,
        float* __restrict__ out_av,
        float* __restrict__ out_ap) {
    extern __shared__ float sm[];
    float* kp_s = sm;                     // 256 * 65
    float* qp_s = kp_s + TK*KPS;          // 8 * 512
    float* w2_s = qp_s + 8*HD;            // 512
    float* sc_p = w2_s + HD;              // 4 * 256 * 8 (partials; [0] = final)
    int*   kl_s = (int*)(sc_p + 4*TK*8);  // 256

    const int qt = blockIdx.x, b = blockIdx.y;
    const int tid = threadIdx.x;
    const int wid = tid >> 5, lane = tid & 31;
    const int cnt = g_kcnt[b];
    const int kcn = (cnt + 31) >> 5;      // # of 32-key chunks (<= 8)
    const int q    = wid & 7;             // q within tile
    const int hsub = wid >> 3;            // 16-h slice within each 64-h chunk

    // stage qp (8 rows), w2, klist
    {
        float4* qp4 = (float4*)qp_s;
        int idx = tid;                    // 1024 float4 total
        int qq = idx >> 7, h4 = idx & 127;
        qp4[idx] = *(const float4*)(g_qp + (size_t)((qt*8 + qq)*BB + b)*HD + h4*4);
        if (tid < 128) ((float4*)w2_s)[tid] = *(const float4*)(W2 + tid*4);
        if (tid < TK) kl_s[tid] = (tid < cnt) ? g_klist[b*TK + tid] : 0;
    }
    __syncthreads();

    // ---- scores over h-chunks of 64; warp works its 16-h slice ----
    float acc[8] = {};
    const int skey = tid & 255, sseg = tid >> 8;   // staging: 4 threads/key
    for (int hc = 0; hc < HD; hc += 64) {
        if (skey < kcn*32) {
            const float4* src = (const float4*)(g_kp + (size_t)(kl_s[skey]*BB + b)*HD + hc + sseg*16);
            float* dst = kp_s + skey*KPS + sseg*16;
            #pragma unroll
            for (int j = 0; j < 4; j++) {
                float4 v = src[j];
                dst[j*4+0] = v.x; dst[j*4+1] = v.y;
                dst[j*4+2] = v.z; dst[j*4+3] = v.w;
            }
        }
        __syncthreads();
        #pragma unroll
        for (int hb = 0; hb < 16; hb += 8) {
            const int h0 = hsub*16 + hb;          // within chunk
            float qv[8], wv[8];
            #pragma unroll
            for (int i = 0; i < 8; i++) {
                qv[i] = qp_s[q*HD + hc + h0 + i];
                wv[i] = w2_s[hc + h0 + i];
            }
            #pragma unroll
            for (int kc = 0; kc < 8; kc++) {
                if (kc >= kcn) break;
                const float* kr = kp_s + (kc*32 + lane)*KPS + h0;
                float a0 = 0.f, a1 = 0.f;
                #pragma unroll
                for (int i = 0; i < 8; i += 2) {
                    a0 += tanha(kr[i]   + qv[i])   * wv[i];
                    a1 += tanha(kr[i+1] + qv[i+1]) * wv[i+1];
                }
                acc[kc] += a0 + a1;
            }
        }
        __syncthreads();
    }
    // write partial scores: sc_p[hsub][ci*8 + q]
    #pragma unroll
    for (int kc = 0; kc < 8; kc++) {
        if (kc >= kcn) break;
        int ci = kc*32 + lane;
        sc_p[hsub*(TK*8) + ci*8 + q] = acc[kc];
    }
    __syncthreads();
    // reduce 4 hsub partials -> sc_p[0]
    {
        int i = tid;                      // 2048 cells, 1024 threads x 2
        #pragma unroll
        for (int r = 0; r < 2; r++, i += 1024) {
            sc_p[i] += sc_p[TK*8 + i] + sc_p[2*TK*8 + i] + sc_p[3*TK*8 + i];
        }
    }
    __syncthreads();

    // ---- masked softmax over keys (warps 0-7: warp = q) ----
    if (wid < 8) {
        const int qq = wid;
        float m = -1e30f;
        for (int ci = lane; ci < cnt; ci += 32) m = fmaxf(m, sc_p[ci*8 + qq]);
        #pragma unroll
        for (int o = 16; o; o >>= 1) m = fmaxf(m, __shfl_xor_sync(0xffffffffu, m, o));
        float s = 0.f;
        for (int ci = lane; ci < cnt; ci += 32) {
            float e = exp2f((sc_p[ci*8 + qq] - m) * 1.4426950408889634f);
            sc_p[ci*8 + qq] = e; s += e;
        }
        #pragma unroll
        for (int o = 16; o; o >>= 1) s += __shfl_xor_sync(0xffffffffu, s, o);
        const float inv = 1.0f / s;
        for (int ci = lane; ci < cnt; ci += 32) {
            float p = sc_p[ci*8 + qq] * inv;
            sc_p[ci*8 + qq] = p;
            out_ap[(size_t)kl_s[ci]*(TQ*BB) + (qt*8 + qq)*BB + b] = p;
        }
    } else if (wid < 16) {
        // warps 8-15: zero-fill masked keys' probs (covers k = 0..255)
        const int k = (wid - 8)*32 + lane;
        if (g_maskdec[b*TK + k]) {
            #pragma unroll
            for (int qq = 0; qq < 8; qq++)
                out_ap[(size_t)k*(TQ*BB) + (qt*8 + qq)*BB + b] = 0.0f;
        }
    }
    __syncthreads();

    // ---- ant_vec[q,b,h] = sum_k p[k,q]*c_key[k,b,h]; tid -> (h, q-half) ----
    {
        const int h = tid & 511, half = tid >> 9;   // half: q 0-3 / 4-7
        float a0=0,a1=0,a2=0,a3=0;
        #pragma unroll 4
        for (int ci = 0; ci < cnt; ci++) {
            float ck = c_key[(size_t)kl_s[ci]*(BB*HD) + b*HD + h];
            float4 p = *(const float4*)&sc_p[ci*8 + half*4];
            a0 += p.x*ck; a1 += p.y*ck; a2 += p.z*ck; a3 += p.w*ck;
        }
        float av[4] = {a0,a1,a2,a3};
        #pragma unroll
        for (int qq = 0; qq < 4; qq++)
            out_av[(size_t)(qt*8 + half*4 + qq)*(BB*HD) + b*HD + h] = av[qq];
    }
}

// ---------------------------------------------------------------------------
extern "C" void kernel_launch(void* const* d_in, const int* in_sizes, int n_in,
                              void* d_out, int out_size) {
    const float* query = (const float*)d_in[0];
    const float* c_key = (const float*)d_in[1];
    const void*  mask  = d_in[2];
    const float* W1    = (const float*)d_in[3];
    const float* b1    = (const float*)d_in[4];
    const float* W2    = (const float*)d_in[5];
    (void)in_sizes; (void)n_in; (void)out_size;

    float* out    = (float*)d_out;
    float* out_av = out;
    float* out_ap = out + (size_t)TQ*BB*HD;

    const size_t smem = (size_t)(TK*KPS + 8*HD + HD + 4*TK*8) * sizeof(float)
                      + (size_t)TK * sizeof(int);   // ~116 KB
    cudaFuncSetAttribute(score_kernel, cudaFuncAttributeMaxDynamicSharedMemorySize,
                         (int)smem);

    mask_prep<<<1, 256>>>(mask);
    convert_kernel<<<512, 256>>>(query, c_key, W1);
    proj_mma<<<dim3(8, 24), 256>>>(b1);
    score_kernel<<<dim3(TQ/8, BB), 1024, smem>>>(c_key, W2, out_av, out_ap);
}

// round 15
// speedup vs baseline: 1.1299x; 1.1299x over previous
#include <cuda_runtime.h>
#include <cuda_bf16.h>
#include <math.h>

#define TQ 128
#define TK 256
#define BB 8
#define HD 512

#define XROWS (TK*BB + TQ*BB)

__device__ float g_kp[TK*BB*HD];
__device__ float g_qp[TQ*BB*HD];
__device__ int   g_klist[BB*TK];
__device__ int   g_kcnt[BB];
__device__ unsigned char g_maskdec[BB*TK];
__device__ __align__(16) __nv_bfloat16 g_xh[XROWS*HD];
__device__ __align__(16) __nv_bfloat16 g_xl[XROWS*HD];
__device__ __align__(16) __nv_bfloat16 g_wh[2*HD*HD];
__device__ __align__(16) __nv_bfloat16 g_wl[2*HD*HD];

__device__ __forceinline__ unsigned pack_bf2(__nv_bfloat16 a, __nv_bfloat16 b) {
    __nv_bfloat162 t(a, b);
    return *(unsigned*)&t;
}

// Blackwell packed f32x2 ops (PTX-only; ptxas never auto-fuses these)
__device__ __forceinline__ float2 fadd2(float2 a, float2 b) {
    unsigned long long ua = reinterpret_cast<unsigned long long&>(a);
    unsigned long long ub = reinterpret_cast<unsigned long long&>(b);
    unsigned long long uo;
    asm("add.rn.f32x2 %0, %1, %2;" : "=l"(uo) : "l"(ua), "l"(ub));
    return reinterpret_cast<float2&>(uo);
}
__device__ __forceinline__ float2 ffma2(float2 a, float2 b, float2 c) {
    unsigned long long ua = reinterpret_cast<unsigned long long&>(a);
    unsigned long long ub = reinterpret_cast<unsigned long long&>(b);
    unsigned long long uc = reinterpret_cast<unsigned long long&>(c);
    unsigned long long uo;
    asm("fma.rn.f32x2 %0, %1, %2, %3;" : "=l"(uo) : "l"(ua), "l"(ub), "l"(uc));
    return reinterpret_cast<float2&>(uo);
}

// ---------------------------------------------------------------------------
// convert: streaming fp32 -> bf16 hi/lo split for c_key, query, W1.
// Block 0 additionally does mask-dtype detect + per-b ballot compaction
// (parallel, ~1 us, overlapped with the other 511 blocks' streaming).
// ---------------------------------------------------------------------------
__global__ void __launch_bounds__(256) convert_kernel(
        const float* __restrict__ query,
        const float* __restrict__ c_key,
        const float* __restrict__ W1,
        const void* __restrict__ mask) {
    if (blockIdx.x == 0) {
        __shared__ int s_isfloat, s_isbig;
        const int tid = threadIdx.x;
        if (tid == 0) { s_isfloat = 0; s_isbig = 0; }
        __syncthreads();
        for (int i = tid; i < 512; i += 256) {
            unsigned v = ((const unsigned*)mask)[i];
            if (v == 0x3f800000u) s_isfloat = 1;
            else if (v > 1u)      s_isbig = 1;
        }
        __syncthreads();
        const int mode = s_isfloat ? 2 : (s_isbig ? 1 : 0);
        const int w = tid >> 5, lane = tid & 31;
        if (w < BB) {
            const int b = w;
            int base = 0;
            #pragma unroll
            for (int c = 0; c < 8; c++) {
                const int k = c * 32 + lane;
                int mk;
                if (mode == 2)      mk = ((const float*)mask)[k*BB + b] != 0.0f;
                else if (mode == 1) mk = ((const unsigned char*)mask)[k*BB + b] != 0;
                else                mk = ((const int*)mask)[k*BB + b] != 0;
                g_maskdec[b*TK + k] = (unsigned char)mk;
                unsigned bal = __ballot_sync(0xffffffffu, !mk);
                if (!mk) {
                    int pos = base + __popc(bal & ((1u << lane) - 1u));
                    g_klist[b*TK + pos] = k;
                }
                base += __popc(bal);
            }
            if (lane == 0) g_kcnt[b] = base;
        }
    }

    const int NCK = (TK*BB*HD)/4;
    const int NQ  = (TQ*BB*HD)/4;
    const int NW  = (2*HD*HD)/4;
    const int total = NCK + NQ + NW;
    const int stride = gridDim.x * blockDim.x;
    for (int i = blockIdx.x*blockDim.x + threadIdx.x; i < total; i += stride) {
        const float4* src; __nv_bfloat16 *H, *L; int e;
        if (i < NCK)          { src = (const float4*)c_key + i;       e = i*4;                  H = g_xh; L = g_xl; }
        else if (i < NCK+NQ)  { src = (const float4*)query + (i-NCK); e = (i-NCK)*4 + TK*BB*HD; H = g_xh; L = g_xl; }
        else                  { src = (const float4*)W1 + (i-NCK-NQ); e = (i-NCK-NQ)*4;         H = g_wh; L = g_wl; }
        float4 v = *src;
        __nv_bfloat16 hx = __float2bfloat16(v.x), hy = __float2bfloat16(v.y);
        __nv_bfloat16 hz = __float2bfloat16(v.z), hw = __float2bfloat16(v.w);
        __nv_bfloat16 lx = __float2bfloat16(v.x - __bfloat162float(hx));
        __nv_bfloat16 ly = __float2bfloat16(v.y - __bfloat162float(hy));
        __nv_bfloat16 lz = __float2bfloat16(v.z - __bfloat162float(hz));
        __nv_bfloat16 lw = __float2bfloat16(v.w - __bfloat162float(hw));
        uint2 hp = make_uint2(pack_bf2(hx,hy), pack_bf2(hz,hw));
        uint2 lp = make_uint2(pack_bf2(lx,ly), pack_bf2(lz,lw));
        *(uint2*)&H[e] = hp;
        *(uint2*)&L[e] = lp;
    }
}

// ---------------------------------------------------------------------------
// Projection GEMM (bf16 hi/lo split, 3 MMA products).  128x64 tile, 256 thr.
// ---------------------------------------------------------------------------
#define LDSM4(R, addr) \
    asm volatile("ldmatrix.sync.aligned.m8n8.x4.shared.b16 {%0,%1,%2,%3}, [%4];" \
        : "=r"(R[0]),"=r"(R[1]),"=r"(R[2]),"=r"(R[3]) : "r"(addr))
#define LDSM4T(R, addr) \
    asm volatile("ldmatrix.sync.aligned.m8n8.x4.trans.shared.b16 {%0,%1,%2,%3}, [%4];" \
        : "=r"(R[0]),"=r"(R[1]),"=r"(R[2]),"=r"(R[3]) : "r"(addr))
#define MMA_BF16(C, A, B0, B1) \
    asm volatile("mma.sync.aligned.m16n8k16.row.col.f32.bf16.bf16.f32 " \
        "{%0,%1,%2,%3},{%4,%5,%6,%7},{%8,%9},{%0,%1,%2,%3};" \
        : "+f"(C[0]),"+f"(C[1]),"+f"(C[2]),"+f"(C[3]) \
        : "r"(A[0]),"r"(A[1]),"r"(A[2]),"r"(A[3]), "r"(B0),"r"(B1))

__global__ void __launch_bounds__(256) proj_mma(const float* __restrict__ b1) {
    __shared__ __align__(16) __nv_bfloat16 Ah[128*64], Al[128*64];
    __shared__ __align__(16) __nv_bfloat16 Bh[64*64],  Bl[64*64];
    const int tid = threadIdx.x, w = tid >> 5, l = tid & 31;
    const int by = blockIdx.y, bn = blockIdx.x * 64;
    const int isQ = (by >= 16);
    const int xrow0 = isQ ? (TK*BB + (by-16)*128) : by*128;
    const int wrow0 = isQ ? HD : 0;
    float* C = isQ ? g_qp : g_kp;
    const int crow0 = isQ ? (by-16)*128 : by*128;
    float acc[8][4] = {};

    for (int kc = 0; kc < HD; kc += 64) {
        #pragma unroll
        for (int t = 0; t < 4; t++) {
            int idx = tid + t*256;
            int r = idx >> 3, c = idx & 7;
            int so = r*64 + ((c ^ (r & 7)) << 3);
            size_t ge = (size_t)(xrow0 + r)*HD + kc + c*8;
            *(uint4*)&Ah[so] = *(const uint4*)&g_xh[ge];
            *(uint4*)&Al[so] = *(const uint4*)&g_xl[ge];
        }
        #pragma unroll
        for (int t = 0; t < 2; t++) {
            int idx = tid + t*256;
            int r = idx >> 3, c = idx & 7;
            int so = r*64 + ((c ^ (r & 7)) << 3);
            size_t ge = (size_t)(wrow0 + kc + r)*HD + bn + c*8;
            *(uint4*)&Bh[so] = *(const uint4*)&g_wh[ge];
            *(uint4*)&Bl[so] = *(const uint4*)&g_wl[ge];
        }
        __syncthreads();
        #pragma unroll
        for (int ks = 0; ks < 4; ks++) {
            int arow = 16*w + (l & 15);
            int ac = ks*2 + (l >> 4);
            unsigned aoff = (unsigned)((arow*64 + ((ac ^ (arow & 7)) << 3)) * 2);
            unsigned ah_a = (unsigned)__cvta_generic_to_shared(Ah) + aoff;
            unsigned al_a = (unsigned)__cvta_generic_to_shared(Al) + aoff;
            unsigned ah[4], al[4];
            LDSM4(ah, ah_a); LDSM4(al, al_a);
            #pragma unroll
            for (int nt = 0; nt < 4; nt++) {
                int brow = ks*16 + (l & 15);
                int bc = nt*2 + (l >> 4);
                unsigned boff = (unsigned)((brow*64 + ((bc ^ (brow & 7)) << 3)) * 2);
                unsigned bh_a = (unsigned)__cvta_generic_to_shared(Bh) + boff;
                unsigned bl_a = (unsigned)__cvta_generic_to_shared(Bl) + boff;
                unsigned bh[4], bl[4];
                LDSM4T(bh, bh_a); LDSM4T(bl, bl_a);
                MMA_BF16(acc[2*nt],   ah, bh[0], bh[1]);
                MMA_BF16(acc[2*nt],   ah, bl[0], bl[1]);
                MMA_BF16(acc[2*nt],   al, bh[0], bh[1]);
                MMA_BF16(acc[2*nt+1], ah, bh[2], bh[3]);
                MMA_BF16(acc[2*nt+1], ah, bl[2], bl[3]);
                MMA_BF16(acc[2*nt+1], al, bh[2], bh[3]);
            }
        }
        __syncthreads();
    }
    const int g = l >> 2, tig = l & 3;
    const int row = crow0 + 16*w + g;
    #pragma unroll
    for (int t = 0; t < 8; t++) {
        const int col = bn + t*8 + tig*2;
        float v0 = 0.f, v1 = 0.f;
        if (isQ) { v0 = b1[col]; v1 = b1[col+1]; }
        C[(size_t)row*HD + col]       = acc[t][0] + v0;
        C[(size_t)row*HD + col+1]     = acc[t][1] + v1;
        C[(size_t)(row+8)*HD + col]   = acc[t][2] + v0;
        C[(size_t)(row+8)*HD + col+1] = acc[t][3] + v1;
    }
}

// ---------------------------------------------------------------------------
__device__ __forceinline__ float tanha(float x) {
    float y;
    asm("tanh.approx.f32 %0, %1;" : "=f"(y) : "f"(x));
    return y;
}

// ---------------------------------------------------------------------------
// Fused score + masked softmax + ant_vec  (R8 structure + f32x2 packed math).
// q-tile = 4.  Grid (32 q-tiles, 8 b) = 256 blocks; 512 thr; 2 blocks/SM.
// Warp per key (stride 16); lanes span h: coalesced kv LDG (L2-resident),
// conflict-free qv/wv LDS; NO mainloop syncs.
// ---------------------------------------------------------------------------
#define QT 4
__global__ void __launch_bounds__(512, 2) score_kernel(
        const float* __restrict__ c_key,
        const float* __restrict__ W2,
        float* __restrict__ out_av,
        float* __restrict__ out_ap) {
    __shared__ float qp_s[QT*HD];
    __shared__ float w2_s[HD];
    __shared__ float sc_s[TK*QT];
    __shared__ int   kl_s[TK];

    const int qt = blockIdx.x, b = blockIdx.y;
    const int tid = threadIdx.x;
    const int cnt = g_kcnt[b];
    const int wid = tid >> 5, lane = tid & 31;

    {
        float4* qp4 = (float4*)qp_s;
        #pragma unroll
        for (int i = tid; i < QT*HD/4; i += 512) {
            int qq = i >> 7, h4 = i & 127;
            qp4[i] = *(const float4*)(g_qp + (size_t)((qt*QT + qq)*BB + b)*HD + h4*4);
        }
        if (tid < 128) ((float4*)w2_s)[tid] = *(const float4*)(W2 + tid*4);
        if (tid < TK) kl_s[tid] = (tid < cnt) ? g_klist[b*TK + tid] : 0;
    }
    __syncthreads();

    // ---- scores: warp j handles keys ci = j, j+16, ... ----
    const float4* qp4 = (const float4*)qp_s;
    float2 wv01[4], wv23[4];
    #pragma unroll
    for (int i = 0; i < 4; i++) {
        float4 w4 = ((const float4*)w2_s)[lane + 32*i];
        wv01[i] = make_float2(w4.x, w4.y);
        wv23[i] = make_float2(w4.z, w4.w);
    }

    for (int ci = wid; ci < cnt; ci += 16) {
        const float4* kr = (const float4*)(g_kp + (size_t)(kl_s[ci]*BB + b)*HD);
        float2 acc2[QT];
        #pragma unroll
        for (int q = 0; q < QT; q++) acc2[q] = make_float2(0.f, 0.f);
        #pragma unroll
        for (int i = 0; i < 4; i++) {
            float4 kv = kr[lane + 32*i];
            float2 kv01 = make_float2(kv.x, kv.y);
            float2 kv23 = make_float2(kv.z, kv.w);
            #pragma unroll
            for (int q = 0; q < QT; q++) {
                float4 qv = qp4[q*128 + lane + 32*i];
                float2 d01 = fadd2(kv01, make_float2(qv.x, qv.y));
                float2 d23 = fadd2(kv23, make_float2(qv.z, qv.w));
                float2 t01 = make_float2(tanha(d01.x), tanha(d01.y));
                float2 t23 = make_float2(tanha(d23.x), tanha(d23.y));
                acc2[q] = ffma2(t01, wv01[i], acc2[q]);
                acc2[q] = ffma2(t23, wv23[i], acc2[q]);
            }
        }
        float acc[QT];
        #pragma unroll
        for (int q = 0; q < QT; q++) {
            acc[q] = acc2[q].x + acc2[q].y;
            #pragma unroll
            for (int o = 16; o; o >>= 1)
                acc[q] += __shfl_xor_sync(0xffffffffu, acc[q], o);
        }
        if (lane == 0)
            *(float4*)&sc_s[ci*QT] = make_float4(acc[0], acc[1], acc[2], acc[3]);
    }
    __syncthreads();

    // ---- masked softmax over k (warps 0-3) + zero-fill masked (warps 4-11) --
    if (wid < QT) {
        const int qq = wid;
        float m = -1e30f;
        for (int ci = lane; ci < cnt; ci += 32) m = fmaxf(m, sc_s[ci*QT + qq]);
        #pragma unroll
        for (int o = 16; o; o >>= 1) m = fmaxf(m, __shfl_xor_sync(0xffffffffu, m, o));
        float s = 0.f;
        for (int ci = lane; ci < cnt; ci += 32) {
            float e = exp2f((sc_s[ci*QT + qq] - m) * 1.4426950408889634f);
            sc_s[ci*QT + qq] = e; s += e;
        }
        #pragma unroll
        for (int o = 16; o; o >>= 1) s += __shfl_xor_sync(0xffffffffu, s, o);
        const float inv = 1.0f / s;
        for (int ci = lane; ci < cnt; ci += 32) {
            float p = sc_s[ci*QT + qq] * inv;
            sc_s[ci*QT + qq] = p;
            out_ap[(size_t)kl_s[ci]*(TQ*BB) + (qt*QT + qq)*BB + b] = p;
        }
    } else if (wid < QT + 8) {
        const int k = (wid - QT)*32 + lane;
        if (g_maskdec[b*TK + k]) {
            #pragma unroll
            for (int qq = 0; qq < QT; qq++)
                out_ap[(size_t)k*(TQ*BB) + (qt*QT + qq)*BB + b] = 0.0f;
        }
    }
    __syncthreads();

    // ---- ant_vec[q,b,h] = sum_k p[k,q] * c_key[k,b,h] ----
    const int h = tid;
    float a0=0,a1=0,a2=0,a3=0;
    #pragma unroll 8
    for (int ci = 0; ci < cnt; ci++) {
        float ck = c_key[(size_t)kl_s[ci]*(BB*HD) + b*HD + h];
        float4 p = *(const float4*)&sc_s[ci*QT];
        a0 += p.x*ck; a1 += p.y*ck; a2 += p.z*ck; a3 += p.w*ck;
    }
    float av[QT] = {a0,a1,a2,a3};
    #pragma unroll
    for (int qq = 0; qq < QT; qq++)
        out_av[(size_t)(qt*QT + qq)*(BB*HD) + b*HD + h] = av[qq];
}

// ---------------------------------------------------------------------------
extern "C" void kernel_launch(void* const* d_in, const int* in_sizes, int n_in,
                              void* d_out, int out_size) {
    const float* query = (const float*)d_in[0];
    const float* c_key = (const float*)d_in[1];
    const void*  mask  = d_in[2];
    const float* W1    = (const float*)d_in[3];
    const float* b1    = (const float*)d_in[4];
    const float* W2    = (const float*)d_in[5];
    (void)in_sizes; (void)n_in; (void)out_size;

    float* out    = (float*)d_out;
    float* out_av = out;
    float* out_ap = out + (size_t)TQ*BB*HD;

    convert_kernel<<<512, 256>>>(query, c_key, W1, mask);
    proj_mma<<<dim3(8, 24), 256>>>(b1);
    score_kernel<<<dim3(TQ/QT, BB), 512>>>(c_key, W2, out_av, out_ap);
}

// round 17
// speedup vs baseline: 1.2689x; 1.1231x over previous
#include <cuda_runtime.h>
#include <cuda_bf16.h>
#include <cuda_fp16.h>
#include <math.h>

#define TQ 128
#define TK 256
#define BB 8
#define HD 512

#define XROWS (TK*BB + TQ*BB)

__device__ int   g_klist[BB*TK];
__device__ int   g_kcnt[BB];
__device__ unsigned char g_maskdec[BB*TK];
__device__ __align__(16) __half g_kp16[TK*BB*HD];   // k projection, fp16
__device__ __align__(16) __half g_qp16[TQ*BB*HD];   // q projection (+b1), fp16
__device__ __align__(16) __nv_bfloat16 g_xh[XROWS*HD];
__device__ __align__(16) __nv_bfloat16 g_xl[XROWS*HD];
__device__ __align__(16) __nv_bfloat16 g_wh[2*HD*HD];
__device__ __align__(16) __nv_bfloat16 g_wl[2*HD*HD];

__device__ __forceinline__ unsigned pack_bf2(__nv_bfloat16 a, __nv_bfloat16 b) {
    __nv_bfloat162 t(a, b);
    return *(unsigned*)&t;
}

// packed fp16x2 helpers
__device__ __forceinline__ unsigned hadd2u(unsigned a, unsigned b) {
    unsigned y; asm("add.rn.f16x2 %0, %1, %2;" : "=r"(y) : "r"(a), "r"(b)); return y;
}
__device__ __forceinline__ unsigned tanh2(unsigned x) {
    unsigned y; asm("tanh.approx.f16x2 %0, %1;" : "=r"(y) : "r"(x)); return y;
}
__device__ __forceinline__ float2 h2f2(unsigned h) {
    __half2 hh = *reinterpret_cast<__half2*>(&h);
    return __half22float2(hh);
}
__device__ __forceinline__ float2 ffma2(float2 a, float2 b, float2 c) {
    unsigned long long ua = reinterpret_cast<unsigned long long&>(a);
    unsigned long long ub = reinterpret_cast<unsigned long long&>(b);
    unsigned long long uc = reinterpret_cast<unsigned long long&>(c);
    unsigned long long uo;
    asm("fma.rn.f32x2 %0, %1, %2, %3;" : "=l"(uo) : "l"(ua), "l"(ub), "l"(uc));
    return reinterpret_cast<float2&>(uo);
}

// ---------------------------------------------------------------------------
// convert: streaming fp32 -> bf16 hi/lo split for c_key, query, W1.
// Block 0 additionally does mask-dtype detect + per-b ballot compaction.
// ---------------------------------------------------------------------------
__global__ void __launch_bounds__(256) convert_kernel(
        const float* __restrict__ query,
        const float* __restrict__ c_key,
        const float* __restrict__ W1,
        const void* __restrict__ mask) {
    if (blockIdx.x == 0) {
        __shared__ int s_isfloat, s_isbig;
        const int tid = threadIdx.x;
        if (tid == 0) { s_isfloat = 0; s_isbig = 0; }
        __syncthreads();
        for (int i = tid; i < 512; i += 256) {
            unsigned v = ((const unsigned*)mask)[i];
            if (v == 0x3f800000u) s_isfloat = 1;
            else if (v > 1u)      s_isbig = 1;
        }
        __syncthreads();
        const int mode = s_isfloat ? 2 : (s_isbig ? 1 : 0);
        const int w = tid >> 5, lane = tid & 31;
        if (w < BB) {
            const int b = w;
            int base = 0;
            #pragma unroll
            for (int c = 0; c < 8; c++) {
                const int k = c * 32 + lane;
                int mk;
                if (mode == 2)      mk = ((const float*)mask)[k*BB + b] != 0.0f;
                else if (mode == 1) mk = ((const unsigned char*)mask)[k*BB + b] != 0;
                else                mk = ((const int*)mask)[k*BB + b] != 0;
                g_maskdec[b*TK + k] = (unsigned char)mk;
                unsigned bal = __ballot_sync(0xffffffffu, !mk);
                if (!mk) {
                    int pos = base + __popc(bal & ((1u << lane) - 1u));
                    g_klist[b*TK + pos] = k;
                }
                base += __popc(bal);
            }
            if (lane == 0) g_kcnt[b] = base;
        }
    }

    const int NCK = (TK*BB*HD)/4;
    const int NQ  = (TQ*BB*HD)/4;
    const int NW  = (2*HD*HD)/4;
    const int total = NCK + NQ + NW;
    const int stride = gridDim.x * blockDim.x;
    for (int i = blockIdx.x*blockDim.x + threadIdx.x; i < total; i += stride) {
        const float4* src; __nv_bfloat16 *H, *L; int e;
        if (i < NCK)          { src = (const float4*)c_key + i;       e = i*4;                  H = g_xh; L = g_xl; }
        else if (i < NCK+NQ)  { src = (const float4*)query + (i-NCK); e = (i-NCK)*4 + TK*BB*HD; H = g_xh; L = g_xl; }
        else                  { src = (const float4*)W1 + (i-NCK-NQ); e = (i-NCK-NQ)*4;         H = g_wh; L = g_wl; }
        float4 v = *src;
        __nv_bfloat16 hx = __float2bfloat16(v.x), hy = __float2bfloat16(v.y);
        __nv_bfloat16 hz = __float2bfloat16(v.z), hw = __float2bfloat16(v.w);
        __nv_bfloat16 lx = __float2bfloat16(v.x - __bfloat162float(hx));
        __nv_bfloat16 ly = __float2bfloat16(v.y - __bfloat162float(hy));
        __nv_bfloat16 lz = __float2bfloat16(v.z - __bfloat162float(hz));
        __nv_bfloat16 lw = __float2bfloat16(v.w - __bfloat162float(hw));
        uint2 hp = make_uint2(pack_bf2(hx,hy), pack_bf2(hz,hw));
        uint2 lp = make_uint2(pack_bf2(lx,ly), pack_bf2(lz,lw));
        *(uint2*)&H[e] = hp;
        *(uint2*)&L[e] = lp;
    }
}

// ---------------------------------------------------------------------------
// Projection GEMM (bf16 hi/lo split, 3 MMA products).  128x64 tile, 256 thr.
// Epilogue writes fp16 directly (score path consumes fp16).
// ---------------------------------------------------------------------------
#define LDSM4(R, addr) \
    asm volatile("ldmatrix.sync.aligned.m8n8.x4.shared.b16 {%0,%1,%2,%3}, [%4];" \
        : "=r"(R[0]),"=r"(R[1]),"=r"(R[2]),"=r"(R[3]) : "r"(addr))
#define LDSM4T(R, addr) \
    asm volatile("ldmatrix.sync.aligned.m8n8.x4.trans.shared.b16 {%0,%1,%2,%3}, [%4];" \
        : "=r"(R[0]),"=r"(R[1]),"=r"(R[2]),"=r"(R[3]) : "r"(addr))
#define MMA_BF16(C, A, B0, B1) \
    asm volatile("mma.sync.aligned.m16n8k16.row.col.f32.bf16.bf16.f32 " \
        "{%0,%1,%2,%3},{%4,%5,%6,%7},{%8,%9},{%0,%1,%2,%3};" \
        : "+f"(C[0]),"+f"(C[1]),"+f"(C[2]),"+f"(C[3]) \
        : "r"(A[0]),"r"(A[1]),"r"(A[2]),"r"(A[3]), "r"(B0),"r"(B1))

__global__ void __launch_bounds__(256) proj_mma(const float* __restrict__ b1) {
    __shared__ __align__(16) __nv_bfloat16 Ah[128*64], Al[128*64];
    __shared__ __align__(16) __nv_bfloat16 Bh[64*64],  Bl[64*64];
    const int tid = threadIdx.x, w = tid >> 5, l = tid & 31;
    const int by = blockIdx.y, bn = blockIdx.x * 64;
    const int isQ = (by >= 16);
    const int xrow0 = isQ ? (TK*BB + (by-16)*128) : by*128;
    const int wrow0 = isQ ? HD : 0;
    __half* C16 = isQ ? g_qp16 : g_kp16;
    const int crow0 = isQ ? (by-16)*128 : by*128;
    float acc[8][4] = {};

    for (int kc = 0; kc < HD; kc += 64) {
        #pragma unroll
        for (int t = 0; t < 4; t++) {
            int idx = tid + t*256;
            int r = idx >> 3, c = idx & 7;
            int so = r*64 + ((c ^ (r & 7)) << 3);
            size_t ge = (size_t)(xrow0 + r)*HD + kc + c*8;
            *(uint4*)&Ah[so] = *(const uint4*)&g_xh[ge];
            *(uint4*)&Al[so] = *(const uint4*)&g_xl[ge];
        }
        #pragma unroll
        for (int t = 0; t < 2; t++) {
            int idx = tid + t*256;
            int r = idx >> 3, c = idx & 7;
            int so = r*64 + ((c ^ (r & 7)) << 3);
            size_t ge = (size_t)(wrow0 + kc + r)*HD + bn + c*8;
            *(uint4*)&Bh[so] = *(const uint4*)&g_wh[ge];
            *(uint4*)&Bl[so] = *(const uint4*)&g_wl[ge];
        }
        __syncthreads();
        #pragma unroll
        for (int ks = 0; ks < 4; ks++) {
            int arow = 16*w + (l & 15);
            int ac = ks*2 + (l >> 4);
            unsigned aoff = (unsigned)((arow*64 + ((ac ^ (arow & 7)) << 3)) * 2);
            unsigned ah_a = (unsigned)__cvta_generic_to_shared(Ah) + aoff;
            unsigned al_a = (unsigned)__cvta_generic_to_shared(Al) + aoff;
            unsigned ah[4], al[4];
            LDSM4(ah, ah_a); LDSM4(al, al_a);
            #pragma unroll
            for (int nt = 0; nt < 4; nt++) {
                int brow = ks*16 + (l & 15);
                int bc = nt*2 + (l >> 4);
                unsigned boff = (unsigned)((brow*64 + ((bc ^ (brow & 7)) << 3)) * 2);
                unsigned bh_a = (unsigned)__cvta_generic_to_shared(Bh) + boff;
                unsigned bl_a = (unsigned)__cvta_generic_to_shared(Bl) + boff;
                unsigned bh[4], bl[4];
                LDSM4T(bh, bh_a); LDSM4T(bl, bl_a);
                MMA_BF16(acc[2*nt],   ah, bh[0], bh[1]);
                MMA_BF16(acc[2*nt],   ah, bl[0], bl[1]);
                MMA_BF16(acc[2*nt],   al, bh[0], bh[1]);
                MMA_BF16(acc[2*nt+1], ah, bh[2], bh[3]);
                MMA_BF16(acc[2*nt+1], ah, bl[2], bl[3]);
                MMA_BF16(acc[2*nt+1], al, bh[2], bh[3]);
            }
        }
        __syncthreads();
    }
    const int g = l >> 2, tig = l & 3;
    const int row = crow0 + 16*w + g;
    #pragma unroll
    for (int t = 0; t < 8; t++) {
        const int col = bn + t*8 + tig*2;   // even
        float v0 = 0.f, v1 = 0.f;
        if (isQ) { v0 = b1[col]; v1 = b1[col+1]; }
        __half2 h01 = __floats2half2_rn(acc[t][0] + v0, acc[t][1] + v1);
        __half2 h23 = __floats2half2_rn(acc[t][2] + v0, acc[t][3] + v1);
        *(__half2*)&C16[(size_t)row*HD + col]     = h01;
        *(__half2*)&C16[(size_t)(row+8)*HD + col] = h23;
    }
}

// ---------------------------------------------------------------------------
// Fused score + masked softmax + ant_vec  (R8 layout, fp16x2 tanh path).
// q-tile = 4.  Grid (32 q-tiles, 8 b) = 256 blocks; 512 thr; 2 blocks/SM.
// Warp per key (stride 16); lane covers h in {8l..8l+7} u {256+8l..+7}.
// kv: 2 coalesced LDG.128 (fp16); qv: LDS.128 from fp16 smem; w2 in f32 regs.
// tanh.approx.f16x2 halves the MUFU stream; accumulate in f32 (ffma2).
// ---------------------------------------------------------------------------
#define QT 4
__global__ void __launch_bounds__(512, 2) score_kernel(
        const float* __restrict__ c_key,
        const float* __restrict__ W2,
        float* __restrict__ out_av,
        float* __restrict__ out_ap) {
    __shared__ __align__(16) __half qp16_s[QT*HD];
    __shared__ float w2_s[HD];
    __shared__ float sc_s[TK*QT];
    __shared__ int   kl_s[TK];

    const int qt = blockIdx.x, b = blockIdx.y;
    const int tid = threadIdx.x;
    const int cnt = g_kcnt[b];
    const int wid = tid >> 5, lane = tid & 31;

    {
        uint4* qp4 = (uint4*)qp16_s;                 // 256 uint4
        for (int i = tid; i < QT*HD/8; i += 512) {
            int qq = i >> 6, c8 = i & 63;
            qp4[i] = *(const uint4*)(g_qp16 + (size_t)((qt*QT + qq)*BB + b)*HD + c8*8);
        }
        if (tid < 128) ((float4*)w2_s)[tid] = *(const float4*)(W2 + tid*4);
        if (tid < TK) kl_s[tid] = (tid < cnt) ? g_klist[b*TK + tid] : 0;
    }
    __syncthreads();

    // hoist w2 (f32) for this lane's h set
    const float2* w2f2 = (const float2*)w2_s;
    float2 wvA[4], wvB[4];
    #pragma unroll
    for (int j = 0; j < 4; j++) {
        wvA[j] = w2f2[4*lane + j];          // h = 8l .. 8l+7
        wvB[j] = w2f2[128 + 4*lane + j];    // h = 256+8l ..
    }
    const uint4* qps4 = (const uint4*)qp16_s;

    for (int ci = wid; ci < cnt; ci += 16) {
        const uint4* kr = (const uint4*)(g_kp16 + (size_t)(kl_s[ci]*BB + b)*HD);
        uint4 kv0 = kr[lane];        // h = 8l..8l+7 (8 halves)
        uint4 kv1 = kr[32 + lane];   // h = 256+8l..
        float2 acc2[QT];
        #pragma unroll
        for (int q = 0; q < QT; q++) acc2[q] = make_float2(0.f, 0.f);
        #pragma unroll
        for (int q = 0; q < QT; q++) {
            uint4 qv0 = qps4[q*64 + lane];
            uint4 qv1 = qps4[q*64 + 32 + lane];
            acc2[q] = ffma2(h2f2(tanh2(hadd2u(kv0.x, qv0.x))), wvA[0], acc2[q]);
            acc2[q] = ffma2(h2f2(tanh2(hadd2u(kv0.y, qv0.y))), wvA[1], acc2[q]);
            acc2[q] = ffma2(h2f2(tanh2(hadd2u(kv0.z, qv0.z))), wvA[2], acc2[q]);
            acc2[q] = ffma2(h2f2(tanh2(hadd2u(kv0.w, qv0.w))), wvA[3], acc2[q]);
            acc2[q] = ffma2(h2f2(tanh2(hadd2u(kv1.x, qv1.x))), wvB[0], acc2[q]);
            acc2[q] = ffma2(h2f2(tanh2(hadd2u(kv1.y, qv1.y))), wvB[1], acc2[q]);
            acc2[q] = ffma2(h2f2(tanh2(hadd2u(kv1.z, qv1.z))), wvB[2], acc2[q]);
            acc2[q] = ffma2(h2f2(tanh2(hadd2u(kv1.w, qv1.w))), wvB[3], acc2[q]);
        }
        float acc[QT];
        #pragma unroll
        for (int q = 0; q < QT; q++) {
            acc[q] = acc2[q].x + acc2[q].y;
            #pragma unroll
            for (int o = 16; o; o >>= 1)
                acc[q] += __shfl_xor_sync(0xffffffffu, acc[q], o);
        }
        if (lane == 0)
            *(float4*)&sc_s[ci*QT] = make_float4(acc[0], acc[1], acc[2], acc[3]);
    }
    __syncthreads();

    // ---- masked softmax over k (warps 0-3) + zero-fill masked (warps 4-11) --
    if (wid < QT) {
        const int qq = wid;
        float m = -1e30f;
        for (int ci = lane; ci < cnt; ci += 32) m = fmaxf(m, sc_s[ci*QT + qq]);
        #pragma unroll
        for (int o = 16; o; o >>= 1) m = fmaxf(m, __shfl_xor_sync(0xffffffffu, m, o));
        float s = 0.f;
        for (int ci = lane; ci < cnt; ci += 32) {
            float e = exp2f((sc_s[ci*QT + qq] - m) * 1.4426950408889634f);
            sc_s[ci*QT + qq] = e; s += e;
        }
        #pragma unroll
        for (int o = 16; o; o >>= 1) s += __shfl_xor_sync(0xffffffffu, s, o);
        const float inv = 1.0f / s;
        for (int ci = lane; ci < cnt; ci += 32) {
            float p = sc_s[ci*QT + qq] * inv;
            sc_s[ci*QT + qq] = p;
            out_ap[(size_t)kl_s[ci]*(TQ*BB) + (qt*QT + qq)*BB + b] = p;
        }
    } else if (wid < QT + 8) {
        const int k = (wid - QT)*32 + lane;
        if (g_maskdec[b*TK + k]) {
            #pragma unroll
            for (int qq = 0; qq < QT; qq++)
                out_ap[(size_t)k*(TQ*BB) + (qt*QT + qq)*BB + b] = 0.0f;
        }
    }
    __syncthreads();

    // ---- ant_vec[q,b,h] = sum_k p[k,q] * c_key[k,b,h] ----
    const int h = tid;
    float a0=0,a1=0,a2=0,a3=0;
    #pragma unroll 8
    for (int ci = 0; ci < cnt; ci++) {
        float ck = c_key[(size_t)kl_s[ci]*(BB*HD) + b*HD + h];
        float4 p = *(const float4*)&sc_s[ci*QT];
        a0 += p.x*ck; a1 += p.y*ck; a2 += p.z*ck; a3 += p.w*ck;
    }
    float av[QT] = {a0,a1,a2,a3};
    #pragma unroll
    for (int qq = 0; qq < QT; qq++)
        out_av[(size_t)(qt*QT + qq)*(BB*HD) + b*HD + h] = av[qq];
}

// ---------------------------------------------------------------------------
extern "C" void kernel_launch(void* const* d_in, const int* in_sizes, int n_in,
                              void* d_out, int out_size) {
    const float* query = (const float*)d_in[0];
    const float* c_key = (const float*)d_in[1];
    const void*  mask  = d_in[2];
    const float* W1    = (const float*)d_in[3];
    const float* b1    = (const float*)d_in[4];
    const float* W2    = (const float*)d_in[5];
    (void)in_sizes; (void)n_in; (void)out_size;

    float* out    = (float*)d_out;
    float* out_av = out;
    float* out_ap = out + (size_t)TQ*BB*HD;

    convert_kernel<<<512, 256>>>(query, c_key, W1, mask);
    proj_mma<<<dim3(8, 24), 256>>>(b1);
    score_kernel<<<dim3(TQ/QT, BB), 512>>>(c_key, W2, out_av, out_ap);
}